// round 1
// baseline (speedup 1.0000x reference)
#include <cuda_runtime.h>
#include <math.h>

// ---------------------------------------------------------------------------
// Problem shapes
//   x0: [2, 256, 32^3]   -> 512 channel-slices of 32768 elems
//   x1: [2, 128, 64^3]   -> 256 channel-slices of 262144 elems
//   x2: [2,  64, 128^3]  -> 128 channel-slices of 2097152 elems
// Partial-sum layout (deterministic, no atomics):
//   x2: 32 partials/slice  -> 128*32 = 4096   at g_part[0]
//   x1:  4 partials/slice  -> 256*4  = 1024   at g_part[4096]
//   x0:  1 partial /slice  -> 512             at g_part[5120]
// ---------------------------------------------------------------------------

__device__ float g_part[5632];

__global__ __launch_bounds__(256) void gap_reduce(
    const float* __restrict__ x0,
    const float* __restrict__ x1,
    const float* __restrict__ x2)
{
    int bid = blockIdx.x;
    const float4* src;
    int nvec;
    if (bid < 4096) {                      // x2 chunks: 65536 floats each
        src  = reinterpret_cast<const float4*>(x2) + (size_t)bid * 16384;
        nvec = 16384;
    } else if (bid < 5120) {               // x1 chunks: 65536 floats each
        src  = reinterpret_cast<const float4*>(x1) + (size_t)(bid - 4096) * 16384;
        nvec = 16384;
    } else {                               // x0 chunks: 32768 floats each
        src  = reinterpret_cast<const float4*>(x0) + (size_t)(bid - 5120) * 8192;
        nvec = 8192;
    }

    float s = 0.f;
    #pragma unroll 4
    for (int i = threadIdx.x; i < nvec; i += 256) {
        float4 a = src[i];
        s += (a.x + a.y) + (a.z + a.w);
    }

    __shared__ float sbuf[8];
    #pragma unroll
    for (int o = 16; o; o >>= 1) s += __shfl_down_sync(0xffffffffu, s, o);
    if ((threadIdx.x & 31) == 0) sbuf[threadIdx.x >> 5] = s;
    __syncthreads();
    if (threadIdx.x < 8) {
        s = sbuf[threadIdx.x];
        #pragma unroll
        for (int o = 4; o; o >>= 1) s += __shfl_down_sync(0x000000ffu, s, o);
        if (threadIdx.x == 0) g_part[bid] = s;
    }
}

// ---------------------------------------------------------------------------
// Epilogue: single block, 448 threads.
// ---------------------------------------------------------------------------

__device__ __forceinline__ float block_sum(float v, float* sbuf)
{
    #pragma unroll
    for (int o = 16; o; o >>= 1) v += __shfl_down_sync(0xffffffffu, v, o);
    int lane = threadIdx.x & 31;
    int w    = threadIdx.x >> 5;           // 14 warps for 448 threads
    if (lane == 0) sbuf[w] = v;
    __syncthreads();
    if (w == 0) {
        v = (lane < 14) ? sbuf[lane] : 0.f;
        #pragma unroll
        for (int o = 16; o; o >>= 1) v += __shfl_down_sync(0xffffffffu, v, o);
        if (lane == 0) sbuf[0] = v;
    }
    __syncthreads();
    float r = sbuf[0];
    __syncthreads();
    return r;
}

__device__ __forceinline__ void ln_inplace(float* v, int n,
                                           const float* __restrict__ w,
                                           const float* __restrict__ b,
                                           float* sbuf)
{
    int tid = threadIdx.x;
    float x   = (tid < n) ? v[tid] : 0.f;
    float mu  = block_sum(x, sbuf) / (float)n;
    float d   = (tid < n) ? (x - mu) : 0.f;
    float var = block_sum(d * d, sbuf) / (float)n;
    float r   = rsqrtf(var + 1e-5f);
    if (tid < n) v[tid] = d * r * w[tid] + b[tid];
    __syncthreads();
}

__global__ __launch_bounds__(448) void epilogue(
    const float* __restrict__ ln1w, const float* __restrict__ ln1b,
    const float* __restrict__ ln2w, const float* __restrict__ ln2b,
    const float* __restrict__ ln3w, const float* __restrict__ ln3b,
    const float* __restrict__ ln4w, const float* __restrict__ ln4b,
    const float* __restrict__ ln5w, const float* __restrict__ ln5b,
    const float* __restrict__ mlp_w1, const float* __restrict__ mlp_b1,
    const float* __restrict__ mlp_w2, const float* __restrict__ mlp_b2,
    const float* __restrict__ conv_w, const float* __restrict__ conv_b,
    float* __restrict__ out)
{
    __shared__ float sv[448];    // [v1(64) | v2(128) | v3(256)] workspace
    __shared__ float h1s[64];
    __shared__ float sbuf[16];
    int tid = threadIdx.x;

    for (int b = 0; b < 2; b++) {
        // --- Assemble raw GAP means (deterministic partial-sum ordering) ---
        if (tid < 64) {                     // gap(x2) -> sv[0:64)
            int base = (b * 64 + tid) * 32;
            float s = 0.f;
            #pragma unroll
            for (int k = 0; k < 32; k++) s += g_part[base + k];
            sv[tid] = s * (1.f / 2097152.f);
        }
        if (tid < 128) {                    // gap(x1) -> sv[64:192)
            int base = 4096 + (b * 128 + tid) * 4;
            float s = 0.f;
            #pragma unroll
            for (int k = 0; k < 4; k++) s += g_part[base + k];
            sv[64 + tid] = s * (1.f / 262144.f);
        }
        if (tid < 256) {                    // gap(x0) -> sv[192:448)
            sv[192 + tid] = g_part[5120 + b * 256 + tid] * (1.f / 32768.f);
        }
        __syncthreads();

        // --- LayerNorm chain ---
        ln_inplace(sv,        64, ln1w, ln1b, sbuf);   // v1 = LN(gap(x2))
        ln_inplace(sv +  64, 128, ln2w, ln2b, sbuf);   // v2 = LN(gap(x1))
        ln_inplace(sv + 192, 256, ln3w, ln3b, sbuf);   // v3 = LN(gap(x0))
        ln_inplace(sv +  64, 384, ln4w, ln4b, sbuf);   // LN(concat(v2,v3))
        ln_inplace(sv,       448, ln5w, ln5b, sbuf);   // LN(concat(v1,out))

        // --- h1 = relu(out7 @ W1^T + b1)  [64] ---
        if (tid < 64) {
            float acc = mlp_b1[tid];
            const float* wr = mlp_w1 + tid * 448;
            #pragma unroll 8
            for (int j = 0; j < 448; j++) acc = fmaf(wr[j], sv[j], acc);
            h1s[tid] = fmaxf(acc, 0.f);
        }
        __syncthreads();

        // --- h2 = relu(h1 @ W2^T + b2)  [448] ---
        float h2 = 0.f;
        {
            float acc = mlp_b2[tid];
            const float* wr = mlp_w2 + tid * 64;
            #pragma unroll 8
            for (int i = 0; i < 64; i++) acc = fmaf(wr[i], h1s[i], acc);
            h2 = fmaxf(acc, 0.f);
        }
        __syncthreads();
        sv[tid] = h2;                       // blockDim == 448, all threads write
        __syncthreads();

        // --- o = sigmoid(h2 @ Wc^T + bc)  [64] ---
        if (tid < 64) {
            float acc = conv_b[tid];
            const float* wr = conv_w + tid * 448;
            #pragma unroll 8
            for (int k = 0; k < 448; k++) acc = fmaf(wr[k], sv[k], acc);
            out[b * 64 + tid] = 1.f / (1.f + expf(-acc));
        }
        __syncthreads();
    }
}

// ---------------------------------------------------------------------------

extern "C" void kernel_launch(void* const* d_in, const int* in_sizes, int n_in,
                              void* d_out, int out_size)
{
    const float* x0 = (const float*)d_in[0];
    const float* x1 = (const float*)d_in[1];
    const float* x2 = (const float*)d_in[2];

    gap_reduce<<<5632, 256>>>(x0, x1, x2);

    epilogue<<<1, 448>>>(
        (const float*)d_in[3],  (const float*)d_in[4],   // ln1
        (const float*)d_in[5],  (const float*)d_in[6],   // ln2
        (const float*)d_in[7],  (const float*)d_in[8],   // ln3
        (const float*)d_in[9],  (const float*)d_in[10],  // ln4
        (const float*)d_in[11], (const float*)d_in[12],  // ln5
        (const float*)d_in[13], (const float*)d_in[14],  // mlp1
        (const float*)d_in[15], (const float*)d_in[16],  // mlp2
        (const float*)d_in[17], (const float*)d_in[18],  // conv
        (float*)d_out);
}

// round 2
// speedup vs baseline: 1.5380x; 1.5380x over previous
#include <cuda_runtime.h>
#include <math.h>

// ---------------------------------------------------------------------------
// Shapes
//   x0: [2, 256, 32^3]   -> 512 channel-slices of 32768 elems
//   x1: [2, 128, 64^3]   -> 256 channel-slices of 262144 elems
//   x2: [2,  64, 128^3]  -> 128 channel-slices of 2097152 elems
// Partial-sum layout (deterministic, no atomics):
//   x2: 32 partials/slice -> 4096 at g_part[0]
//   x1:  4 partials/slice -> 1024 at g_part[4096]
//   x0:  1 partial/slice  ->  512 at g_part[5120]
// ---------------------------------------------------------------------------

__device__ float g_part[5632];
__device__ float g_dummy[4];   // sink for L2-warm blocks (never read)

__global__ __launch_bounds__(256) void gap_reduce(
    const float* __restrict__ x0,
    const float* __restrict__ x1,
    const float* __restrict__ x2,
    const float* __restrict__ w_a,   // mlp_w1 (L2 warm)
    const float* __restrict__ w_b,   // mlp_w2 (L2 warm)
    const float* __restrict__ w_c)   // conv_w (L2 warm)
{
    int bid = blockIdx.x;

    // --- L2 warm blocks: pre-touch the big weight matrices (86016 floats) ---
    if (bid >= 5632) {
        const float* w = (bid == 5632) ? w_a : (bid == 5633) ? w_b : w_c;
        const float4* w4 = reinterpret_cast<const float4*>(w);
        float s = 0.f;
        for (int i = threadIdx.x; i < 7168; i += 256) {
            float4 a = w4[i];
            s += (a.x + a.y) + (a.z + a.w);
        }
        if (s == -1.0f && threadIdx.x == 0) g_dummy[bid - 5632] = s; // keep loads live
        return;
    }

    const float4* src;
    int nvec;
    if (bid < 4096) {                      // x2 chunks: 65536 floats each
        src  = reinterpret_cast<const float4*>(x2) + (size_t)bid * 16384;
        nvec = 16384;
    } else if (bid < 5120) {               // x1 chunks: 65536 floats each
        src  = reinterpret_cast<const float4*>(x1) + (size_t)(bid - 4096) * 16384;
        nvec = 16384;
    } else {                               // x0 chunks: 32768 floats each
        src  = reinterpret_cast<const float4*>(x0) + (size_t)(bid - 5120) * 8192;
        nvec = 8192;
    }

    float s = 0.f;
    #pragma unroll 4
    for (int i = threadIdx.x; i < nvec; i += 256) {
        float4 a = __ldcs(src + i);        // streaming: evict-first in L2
        s += (a.x + a.y) + (a.z + a.w);
    }

    __shared__ float sbuf[8];
    #pragma unroll
    for (int o = 16; o; o >>= 1) s += __shfl_down_sync(0xffffffffu, s, o);
    if ((threadIdx.x & 31) == 0) sbuf[threadIdx.x >> 5] = s;
    __syncthreads();
    if (threadIdx.x < 8) {
        s = sbuf[threadIdx.x];
        #pragma unroll
        for (int o = 4; o; o >>= 1) s += __shfl_down_sync(0x000000ffu, s, o);
        if (threadIdx.x == 0) g_part[bid] = s;
    }
}

// ---------------------------------------------------------------------------
// Epilogue: single block, 896 threads. Threads [0,448) = batch 0 (warps 0-13),
// threads [448,896) = batch 1 (warps 14-27).
// ---------------------------------------------------------------------------

// Sum across a 448-thread batch group (warp-aligned).
__device__ __forceinline__ float gsum(float v, float* sbuf)
{
    #pragma unroll
    for (int o = 16; o; o >>= 1) v += __shfl_down_sync(0xffffffffu, v, o);
    int w = threadIdx.x >> 5;          // 0..27
    int lane = threadIdx.x & 31;
    if (lane == 0) sbuf[w] = v;
    __syncthreads();
    if (w == 0 || w == 14) {
        float x = (lane < 14) ? sbuf[w + lane] : 0.f;
        #pragma unroll
        for (int o = 16; o; o >>= 1) x += __shfl_down_sync(0xffffffffu, x, o);
        if (lane == 0) sbuf[w] = x;
    }
    __syncthreads();
    float r = sbuf[(threadIdx.x >= 448) ? 14 : 0];
    __syncthreads();
    return r;
}

__device__ __forceinline__ void ln(float* v, int n, int t,
                                   const float* __restrict__ w,
                                   const float* __restrict__ b,
                                   float* sbuf)
{
    float x   = (t < n) ? v[t] : 0.f;
    float mu  = gsum(x, sbuf) * (1.f / (float)n);
    float d   = (t < n) ? (x - mu) : 0.f;
    float var = gsum(d * d, sbuf) * (1.f / (float)n);
    float r   = rsqrtf(var + 1e-5f);
    if (t < n) v[t] = d * r * w[t] + b[t];
    __syncthreads();
}

__global__ __launch_bounds__(896) void epilogue(
    const float* __restrict__ ln1w, const float* __restrict__ ln1b,
    const float* __restrict__ ln2w, const float* __restrict__ ln2b,
    const float* __restrict__ ln3w, const float* __restrict__ ln3b,
    const float* __restrict__ ln4w, const float* __restrict__ ln4b,
    const float* __restrict__ ln5w, const float* __restrict__ ln5b,
    const float* __restrict__ mlp_w1, const float* __restrict__ mlp_b1,
    const float* __restrict__ mlp_w2, const float* __restrict__ mlp_b2,
    const float* __restrict__ conv_w, const float* __restrict__ conv_b,
    float* __restrict__ out)
{
    __shared__ float sv[2][448];      // LN / activation workspace per batch
    __shared__ float h1s[2][64];
    __shared__ float red[2][448];     // matmul partial-sum buffer
    __shared__ float sbuf[32];

    int tid = threadIdx.x;
    int b   = tid / 448;              // warp-aligned batch split
    int t   = tid - b * 448;
    float* svb = sv[b];

    // --- Assemble raw GAP means (deterministic partial-sum ordering) ---
    if (t < 64) {                     // gap(x2) -> svb[0:64)
        int base = (b * 64 + t) * 32;
        float s = 0.f;
        #pragma unroll
        for (int k = 0; k < 32; k++) s += g_part[base + k];
        svb[t] = s * (1.f / 2097152.f);
    }
    if (t < 128) {                    // gap(x1) -> svb[64:192)
        int base = 4096 + (b * 128 + t) * 4;
        float s = 0.f;
        #pragma unroll
        for (int k = 0; k < 4; k++) s += g_part[base + k];
        svb[64 + t] = s * (1.f / 262144.f);
    }
    if (t < 256) {                    // gap(x0) -> svb[192:448)
        svb[192 + t] = g_part[5120 + b * 256 + t] * (1.f / 32768.f);
    }
    __syncthreads();

    // --- LayerNorm chain (both batches in parallel) ---
    ln(svb,        64, t, ln1w, ln1b, sbuf);   // v1 = LN(gap(x2))
    ln(svb +  64, 128, t, ln2w, ln2b, sbuf);   // v2 = LN(gap(x1))
    ln(svb + 192, 256, t, ln3w, ln3b, sbuf);   // v3 = LN(gap(x0))
    ln(svb +  64, 384, t, ln4w, ln4b, sbuf);   // LN(concat(v2,v3))
    ln(svb,       448, t, ln5w, ln5b, sbuf);   // LN(concat(v1,out))

    int c = t >> 6;                   // inner chunk 0..6
    int i = t & 63;                   // output index 0..63

    // --- h1 = relu(out7 @ W1^T + b1) : 448 threads/batch, chunked inner ---
    {
        const float4* w4 = reinterpret_cast<const float4*>(mlp_w1 + i * 448 + c * 64);
        const float4* x4 = reinterpret_cast<const float4*>(svb + c * 64);
        float p = 0.f;
        #pragma unroll
        for (int k = 0; k < 16; k++) {
            float4 wv = w4[k];
            float4 xv = x4[k];
            p = fmaf(wv.x, xv.x, p);
            p = fmaf(wv.y, xv.y, p);
            p = fmaf(wv.z, xv.z, p);
            p = fmaf(wv.w, xv.w, p);
        }
        red[b][c * 64 + i] = p;
    }
    __syncthreads();
    if (t < 64) {
        float acc = mlp_b1[t];
        #pragma unroll
        for (int cc = 0; cc < 7; cc++) acc += red[b][cc * 64 + t];
        h1s[b][t] = fmaxf(acc, 0.f);
    }
    __syncthreads();

    // --- h2 = relu(h1 @ W2^T + b2) : one output per thread ---
    {
        float acc = mlp_b2[t];
        const float4* w4 = reinterpret_cast<const float4*>(mlp_w2 + t * 64);
        const float4* h4 = reinterpret_cast<const float4*>(h1s[b]);
        #pragma unroll
        for (int k = 0; k < 16; k++) {
            float4 wv = w4[k];
            float4 hv = h4[k];
            acc = fmaf(wv.x, hv.x, acc);
            acc = fmaf(wv.y, hv.y, acc);
            acc = fmaf(wv.z, hv.z, acc);
            acc = fmaf(wv.w, hv.w, acc);
        }
        acc = fmaxf(acc, 0.f);
        __syncthreads();              // sv reads (h1 stage) fully done
        svb[t] = acc;
        __syncthreads();
    }

    // --- o = sigmoid(h2 @ Wc^T + bc) : chunked inner again ---
    {
        const float4* w4 = reinterpret_cast<const float4*>(conv_w + i * 448 + c * 64);
        const float4* x4 = reinterpret_cast<const float4*>(svb + c * 64);
        float p = 0.f;
        #pragma unroll
        for (int k = 0; k < 16; k++) {
            float4 wv = w4[k];
            float4 xv = x4[k];
            p = fmaf(wv.x, xv.x, p);
            p = fmaf(wv.y, xv.y, p);
            p = fmaf(wv.z, xv.z, p);
            p = fmaf(wv.w, xv.w, p);
        }
        red[b][c * 64 + i] = p;
    }
    __syncthreads();
    if (t < 64) {
        float acc = conv_b[t];
        #pragma unroll
        for (int cc = 0; cc < 7; cc++) acc += red[b][cc * 64 + t];
        out[b * 64 + t] = 1.f / (1.f + expf(-acc));
    }
}

// ---------------------------------------------------------------------------

extern "C" void kernel_launch(void* const* d_in, const int* in_sizes, int n_in,
                              void* d_out, int out_size)
{
    const float* x0 = (const float*)d_in[0];
    const float* x1 = (const float*)d_in[1];
    const float* x2 = (const float*)d_in[2];

    gap_reduce<<<5635, 256>>>(x0, x1, x2,
                              (const float*)d_in[13],   // mlp_w1
                              (const float*)d_in[15],   // mlp_w2
                              (const float*)d_in[17]);  // conv_w

    epilogue<<<1, 896>>>(
        (const float*)d_in[3],  (const float*)d_in[4],   // ln1
        (const float*)d_in[5],  (const float*)d_in[6],   // ln2
        (const float*)d_in[7],  (const float*)d_in[8],   // ln3
        (const float*)d_in[9],  (const float*)d_in[10],  // ln4
        (const float*)d_in[11], (const float*)d_in[12],  // ln5
        (const float*)d_in[13], (const float*)d_in[14],  // mlp1
        (const float*)d_in[15], (const float*)d_in[16],  // mlp2
        (const float*)d_in[17], (const float*)d_in[18],  // conv
        (float*)d_out);
}